// round 5
// baseline (speedup 1.0000x reference)
#include <cuda_runtime.h>
#include <math.h>

#define MM 4096      // B*T
#define HH 512
#define G4 2048      // 4*H
#define OO 50257

// ------------- static device scratch (no allocations allowed) -------------
__device__ float    g_xg[(size_t)MM * G4];    // [m][4H], m = b*512 + t
__device__ float    g_hseq[(size_t)MM * HH];  // [m][H]
__device__ float    g_hn[4096];
__device__ float    g_cn[4096];
__device__ unsigned g_bar;

// ------------- helpers -------------
__device__ __forceinline__ unsigned tf32_rna(float x) {
    unsigned y; asm("cvt.rna.tf32.f32 %0, %1;" : "=r"(y) : "f"(x)); return y;
}
__device__ __forceinline__ void mma8(float* d, const unsigned* a, const unsigned* b) {
    asm volatile(
        "mma.sync.aligned.m16n8k8.row.col.f32.tf32.tf32.f32 "
        "{%0,%1,%2,%3}, {%4,%5,%6,%7}, {%8,%9}, {%0,%1,%2,%3};"
        : "+f"(d[0]), "+f"(d[1]), "+f"(d[2]), "+f"(d[3])
        : "r"(a[0]), "r"(a[1]), "r"(a[2]), "r"(a[3]), "r"(b[0]), "r"(b[1]));
}
__device__ __forceinline__ unsigned long long pk2(float x, float y) {
    unsigned long long r; asm("mov.b64 %0, {%1,%2};" : "=l"(r) : "f"(x), "f"(y)); return r;
}
__device__ __forceinline__ unsigned long long fma2(unsigned long long a,
                                                   unsigned long long b,
                                                   unsigned long long c) {
    unsigned long long d;
    asm("fma.rn.f32x2 %0, %1, %2, %3;" : "=l"(d) : "l"(a), "l"(b), "l"(c));
    return d;
}
__device__ __forceinline__ void unpk(unsigned long long v, float& x, float& y) {
    asm("mov.b64 {%0,%1}, %2;" : "=f"(x), "=f"(y) : "l"(v));
}

// ------------- init: reset barrier -------------
__global__ void init_kernel() {
    if (threadIdx.x == 0 && blockIdx.x == 0) g_bar = 0u;
}

// ------- tf32 GEMM: C[m][n] = sum_k A[row(m)][k]*W[n][k] + b1[n](+b2[n]) -------
// Template: NS=2 -> split-tf32 (hi/lo, 3 MMAs, ~fp32 accuracy); K = reduction dim.
// Block 128x128, 256 threads, 8 warps (2m x 4n), warp tile 64x32 via m16n8k8.
template<int NS, int BK, int K>
__global__ __launch_bounds__(256) void gemm_tf32(
    const float* __restrict__ A, const int* __restrict__ gidx,
    const float* __restrict__ W, const float* __restrict__ b1,
    const float* __restrict__ b2, float* __restrict__ C, int N)
{
    __shared__ unsigned As[NS][128][BK + 4];
    __shared__ unsigned Bs[NS][128][BK + 4];

    const int tid  = threadIdx.x;
    const int lane = tid & 31, warp = tid >> 5;
    const int bm   = blockIdx.x * 128, bn = blockIdx.y * 128;
    const int wm   = (warp >> 2) * 64, wn = (warp & 3) * 32;
    const int grp  = lane >> 2, t4 = lane & 3;

    constexpr int KR4 = K / 4;        // float4 per row
    constexpr int TPR = BK / 4;       // threads per row (float4 slots per k-tile)
    constexpr int RPP = 256 / TPR;    // rows per pass
    constexpr int NP  = 128 / RPP;    // passes
    constexpr int KT  = K / BK;       // k tiles
    const int lrow = tid / TPR;
    const int lf4  = tid % TPR;

    const float4* aptr[NP]; const float4* bptr[NP]; bool bv[NP];
#pragma unroll
    for (int i = 0; i < NP; ++i) {
        int m = bm + lrow + RPP * i;
        long arow = gidx ? (long)gidx[m] : (long)m;
        aptr[i] = ((const float4*)A) + arow * KR4;
        int n = bn + lrow + RPP * i;
        bv[i] = (n < N);
        bptr[i] = ((const float4*)W) + (long)(bv[i] ? n : 0) * KR4;
    }

    float acc[4][4][4];
#pragma unroll
    for (int mf = 0; mf < 4; ++mf)
#pragma unroll
        for (int nf = 0; nf < 4; ++nf)
#pragma unroll
            for (int j = 0; j < 4; ++j) acc[mf][nf][j] = 0.f;

    float4 ar4[NP], br4[NP];
#pragma unroll
    for (int i = 0; i < NP; ++i) {
        ar4[i] = __ldg(aptr[i] + lf4);
        br4[i] = bv[i] ? __ldg(bptr[i] + lf4) : make_float4(0.f, 0.f, 0.f, 0.f);
    }

    for (int it = 0; it < KT; ++it) {
#pragma unroll
        for (int i = 0; i < NP; ++i) {
            int col = lrow + RPP * i;
            float av[4] = {ar4[i].x, ar4[i].y, ar4[i].z, ar4[i].w};
            float bw[4] = {br4[i].x, br4[i].y, br4[i].z, br4[i].w};
            uint4 ah, bh;
            ah.x = tf32_rna(av[0]); ah.y = tf32_rna(av[1]);
            ah.z = tf32_rna(av[2]); ah.w = tf32_rna(av[3]);
            bh.x = tf32_rna(bw[0]); bh.y = tf32_rna(bw[1]);
            bh.z = tf32_rna(bw[2]); bh.w = tf32_rna(bw[3]);
            *(uint4*)&As[0][col][lf4 * 4] = ah;
            *(uint4*)&Bs[0][col][lf4 * 4] = bh;
            if (NS == 2) {
                uint4 al, bl;
                al.x = tf32_rna(av[0] - __uint_as_float(ah.x));
                al.y = tf32_rna(av[1] - __uint_as_float(ah.y));
                al.z = tf32_rna(av[2] - __uint_as_float(ah.z));
                al.w = tf32_rna(av[3] - __uint_as_float(ah.w));
                bl.x = tf32_rna(bw[0] - __uint_as_float(bh.x));
                bl.y = tf32_rna(bw[1] - __uint_as_float(bh.y));
                bl.z = tf32_rna(bw[2] - __uint_as_float(bh.z));
                bl.w = tf32_rna(bw[3] - __uint_as_float(bh.w));
                *(uint4*)&As[1][col][lf4 * 4] = al;
                *(uint4*)&Bs[1][col][lf4 * 4] = bl;
            }
        }
        __syncthreads();
        if (it + 1 < KT) {
            int f = (it + 1) * TPR + lf4;
#pragma unroll
            for (int i = 0; i < NP; ++i) {
                ar4[i] = __ldg(aptr[i] + f);
                br4[i] = bv[i] ? __ldg(bptr[i] + f) : make_float4(0.f, 0.f, 0.f, 0.f);
            }
        }
#pragma unroll
        for (int ks = 0; ks < BK / 8; ++ks) {
            const int k0 = ks * 8;
            unsigned af[NS][4][4], bf[NS][4][2];
#pragma unroll
            for (int s = 0; s < NS; ++s) {
#pragma unroll
                for (int mf = 0; mf < 4; ++mf) {
                    int r = wm + mf * 16 + grp;
                    af[s][mf][0] = As[s][r][k0 + t4];
                    af[s][mf][1] = As[s][r + 8][k0 + t4];
                    af[s][mf][2] = As[s][r][k0 + t4 + 4];
                    af[s][mf][3] = As[s][r + 8][k0 + t4 + 4];
                }
#pragma unroll
                for (int nf = 0; nf < 4; ++nf) {
                    int cc = wn + nf * 8 + grp;
                    bf[s][nf][0] = Bs[s][cc][k0 + t4];
                    bf[s][nf][1] = Bs[s][cc][k0 + t4 + 4];
                }
            }
#pragma unroll
            for (int mf = 0; mf < 4; ++mf)
#pragma unroll
                for (int nf = 0; nf < 4; ++nf) {
                    mma8(acc[mf][nf], af[0][mf], bf[0][nf]);
                    if (NS == 2) {
                        mma8(acc[mf][nf], af[0][mf], bf[1][nf]);
                        mma8(acc[mf][nf], af[1][mf], bf[0][nf]);
                    }
                }
        }
        __syncthreads();
    }

    // epilogue
#pragma unroll
    for (int nf = 0; nf < 4; ++nf) {
        int n0 = bn + wn + nf * 8 + 2 * t4;
        int n1 = n0 + 1;
        float e0 = 0.f, e1 = 0.f;
        if (n0 < N) e0 = b1[n0] + (b2 ? b2[n0] : 0.f);
        if (n1 < N) e1 = b1[n1] + (b2 ? b2[n1] : 0.f);
#pragma unroll
        for (int mf = 0; mf < 4; ++mf) {
            long m0 = bm + wm + mf * 16 + grp;
            long m1 = m0 + 8;
            if (n0 < N) {
                C[m0 * (long)N + n0] = acc[mf][nf][0] + e0;
                C[m1 * (long)N + n0] = acc[mf][nf][2] + e0;
            }
            if (n1 < N) {
                C[m0 * (long)N + n1] = acc[mf][nf][1] + e1;
                C[m1 * (long)N + n1] = acc[mf][nf][3] + e1;
            }
        }
    }
}

// ------------- persistent LSTM scan: 128 CTAs x 256 threads -------------
// CTA bx owns hidden units u0..u0+3 (u0 = bx*4), all 4 gates (16 W_hh rows in smem).
// h is published through hseq[b][t][k]; step t stages h from hseq row t-1 (h0 at t=0).
#define WPAD 516
__global__ __launch_bounds__(256) void lstm_kernel(
    const float* __restrict__ xg, const float* __restrict__ Whh,
    const float* __restrict__ h0, const float* __restrict__ c0,
    float* __restrict__ hseq, float* hn_out, float* cn_out)
{
    extern __shared__ float sm[];
    float* W_s  = sm;                   // 16 * WPAD
    float* h_s  = sm + 16 * WPAD;       // 4096, layout (k>>2)*32 + b*4 + (k&3)
    float* gbuf = h_s + 4096;           // 128

    const int tid = threadIdx.x, bx = blockIdx.x;
    const int u0 = bx * 4;

    for (int idx = tid; idx < 16 * 128; idx += 256) {
        int jl = idx >> 7, k4 = idx & 127;
        int gate = jl >> 2, u = u0 + (jl & 3);
        float4 v = __ldg(((const float4*)(Whh + (long)(gate * 512 + u) * 512)) + k4);
        *(float4*)&W_s[jl * WPAD + k4 * 4] = v;
    }

    float c = 0.f; int cu = 0, cb = 0;
    if (tid < 32) { cu = tid >> 3; cb = tid & 7; c = c0[cb * 512 + u0 + cu]; }

    const int warp = tid >> 5, lane = tid & 31;
    const int jl = warp * 2 + ((lane >> 3) & 1);
    const int b  = lane & 7;
    const int half = lane >> 4;
    const float* Wrow  = W_s + jl * WPAD + half * 256;
    const float* hbase = h_s + half * 2048 + b * 4;

    for (int t = 0; t < 512; ++t) {
        float xgi = 0.f, xgf = 0.f, xgg = 0.f, xgo = 0.f;
        if (tid < 32) {
            const float* xr = xg + ((long)cb * 512 + t) * 2048 + u0 + cu;
            xgi = __ldg(xr);        xgf = __ldg(xr + 512);
            xgg = __ldg(xr + 1024); xgo = __ldg(xr + 1536);
        }
        for (int i = tid; i < 1024; i += 256) {
            int k4 = i >> 3, sb = i & 7;
            const float* srow = (t == 0) ? (h0 + (long)sb * 512)
                                         : (hseq + ((long)sb * 512 + (t - 1)) * 512);
            float4 v = __ldcg(((const float4*)srow) + k4);
            *(float4*)&h_s[k4 * 32 + sb * 4] = v;
        }
        __syncthreads();

        unsigned long long a0 = 0ull, a1 = 0ull;
#pragma unroll 8
        for (int kq = 0; kq < 64; ++kq) {
            float4 wv = *(const float4*)(Wrow + kq * 4);
            float4 hv = *(const float4*)(hbase + kq * 32);
            a0 = fma2(pk2(wv.x, wv.y), pk2(hv.x, hv.y), a0);
            a1 = fma2(pk2(wv.z, wv.w), pk2(hv.z, hv.w), a1);
        }
        float s0x, s0y, s1x, s1y;
        unpk(a0, s0x, s0y); unpk(a1, s1x, s1y);
        float v = s0x + s0y + s1x + s1y;
        v += __shfl_xor_sync(0xffffffffu, v, 16);
        if (half == 0) gbuf[jl * 8 + b] = v;
        __syncthreads();

        if (tid < 32) {
            float gi = gbuf[(cu)      * 8 + cb] + xgi;
            float gf = gbuf[(4 + cu)  * 8 + cb] + xgf;
            float gg = gbuf[(8 + cu)  * 8 + cb] + xgg;
            float go = gbuf[(12 + cu) * 8 + cb] + xgo;
            float si = 1.f / (1.f + expf(-gi));
            float sf = 1.f / (1.f + expf(-gf));
            float so = 1.f / (1.f + expf(-go));
            float tg = tanhf(gg);
            c = sf * c + si * tg;
            float hh = so * tanhf(c);
            int k = u0 + cu;
            hseq[((long)cb * 512 + t) * 512 + k] = hh;
            if (t == 511) {
                if (hn_out) hn_out[cb * 512 + k] = hh;
                if (cn_out) cn_out[cb * 512 + k] = c;
            }
        }
        __threadfence();
        __syncthreads();
        if (tid == 0) {
            atomicAdd(&g_bar, 1u);
            unsigned target = 128u * (unsigned)(t + 1);
            unsigned vv;
            do {
                asm volatile("ld.acquire.gpu.global.u32 %0, [%1];"
                             : "=r"(vv) : "l"(&g_bar) : "memory");
            } while (vv < target);
        }
        __syncthreads();
    }
}

// ------------- launch -------------
extern "C" void kernel_launch(void* const* d_in, const int* in_sizes, int n_in,
                              void* d_out, int out_size) {
    const int*   input = (const int*)  d_in[0];
    const float* h0    = (const float*)d_in[1];
    const float* c0    = (const float*)d_in[2];
    const float* emb   = (const float*)d_in[3];   // [V, 256]  (E = 256!)
    const float* W_ih  = (const float*)d_in[4];   // [2048, 256]
    const float* W_hh  = (const float*)d_in[5];   // [2048, 512]
    const float* b_ih  = (const float*)d_in[6];
    const float* b_hh  = (const float*)d_in[7];
    const float* fc_w  = (const float*)d_in[8];   // [50257, 512]
    const float* fc_b  = (const float*)d_in[9];
    float* out = (float*)d_out;

    float* xg;   cudaGetSymbolAddress((void**)&xg,   g_xg);
    float* hseq; cudaGetSymbolAddress((void**)&hseq, g_hseq);
    float* hns;  cudaGetSymbolAddress((void**)&hns,  g_hn);
    float* cns;  cudaGetSymbolAddress((void**)&cns,  g_cn);

    const long MO = (long)MM * OO;
    float* hn = hns; float* cn = cns;
    if ((long)out_size >= MO + 8192) { hn = out + MO; cn = out + MO + 4096; }

    const int lstm_smem = (16 * WPAD + 4096 + 128) * (int)sizeof(float);
    cudaFuncSetAttribute(lstm_kernel, cudaFuncAttributeMaxDynamicSharedMemorySize,
                         lstm_smem);

    init_kernel<<<1, 32>>>();
    // xg = gather(emb)[4096,256] @ W_ih^T[256,2048] + (b_ih + b_hh)
    gemm_tf32<2, 16, 256><<<dim3(32, 16), 256>>>(emb, input, W_ih, b_ih, b_hh,
                                                 xg, G4);
    lstm_kernel<<<128, 256, lstm_smem>>>(xg, W_hh, h0, c0, hseq, hn, cn);
    // out = hseq[4096,512] @ fc_w^T[512,50257] + fc_b
    gemm_tf32<1, 16, 512><<<dim3(32, 393), 256>>>(hseq, nullptr, fc_w, fc_b,
                                                  nullptr, out, OO);
}